// round 6
// baseline (speedup 1.0000x reference)
#include <cuda_runtime.h>
#include <cuda_bf16.h>

#define FGRID 64
#define MAX_N 2000000

// Accumulators + scratch (device globals: allocation-free per harness rules).
// Zero-initialized at module load; k_edge's last block resets them after use,
// so every graph replay starts from zeros.
__device__ double g_accD;
__device__ double g_accR;
__device__ unsigned g_ticket;
__device__ float4 g_W[MAX_N];   // W[i] = V[i] - V_ref[i], padded to 16B: 1-sector gathers

__device__ __forceinline__ void block_reduce_atomic(float v, double* acc) {
    #pragma unroll
    for (int o = 16; o; o >>= 1)
        v += __shfl_xor_sync(0xffffffffu, v, o);
    __shared__ float warp_sums[32];
    int lane = threadIdx.x & 31;
    int wid  = threadIdx.x >> 5;
    if (lane == 0) warp_sums[wid] = v;
    __syncthreads();
    if (wid == 0) {
        int nw = (blockDim.x + 31) >> 5;
        float s = (lane < nw) ? warp_sums[lane] : 0.0f;
        #pragma unroll
        for (int o = 16; o; o >>= 1)
            s += __shfl_xor_sync(0xffffffffu, s, o);
        if (lane == 0) atomicAdd(acc, (double)s);
    }
}

// Kernel A: W = V - V_ref (padded float4) + trilinear distance-field loss
__global__ void k_vertex(const float* __restrict__ V,
                         const float* __restrict__ Vref,
                         const float* __restrict__ field,
                         int N) {
    float acc = 0.0f;
    for (int i = blockIdx.x * blockDim.x + threadIdx.x; i < N;
         i += gridDim.x * blockDim.x) {
        float vx = V[3 * i + 0];
        float vy = V[3 * i + 1];
        float vz = V[3 * i + 2];
        float rx = Vref[3 * i + 0];
        float ry = Vref[3 * i + 1];
        float rz = Vref[3 * i + 2];
        g_W[i] = make_float4(vx - rx, vy - ry, vz - rz, 0.0f);

        float cx = fmaxf(fminf(vx * 63.0f, 62.9999f), 0.0f);
        float cy = fmaxf(fminf(vy * 63.0f, 62.9999f), 0.0f);
        float cz = fmaxf(fminf(vz * 63.0f, 62.9999f), 0.0f);
        int x0 = (int)cx;  float fx = cx - (float)x0;
        int y0 = (int)cy;  float fy = cy - (float)y0;
        int z0 = (int)cz;  float fz = cz - (float)z0;
        int base = x0 * (FGRID * FGRID) + y0 * FGRID + z0;

        float c000 = __ldg(field + base);
        float c001 = __ldg(field + base + 1);
        float c010 = __ldg(field + base + FGRID);
        float c011 = __ldg(field + base + FGRID + 1);
        float c100 = __ldg(field + base + FGRID * FGRID);
        float c101 = __ldg(field + base + FGRID * FGRID + 1);
        float c110 = __ldg(field + base + FGRID * FGRID + FGRID);
        float c111 = __ldg(field + base + FGRID * FGRID + FGRID + 1);

        float c00 = fmaf(fz, c001 - c000, c000);
        float c01 = fmaf(fz, c011 - c010, c010);
        float c10 = fmaf(fz, c101 - c100, c100);
        float c11 = fmaf(fz, c111 - c110, c110);
        float c0  = fmaf(fy, c01 - c00, c00);
        float c1  = fmaf(fy, c11 - c10, c10);
        float d   = fmaf(fx, c1 - c0, c0);

        acc = fmaf(d, d, acc);
    }
    block_reduce_atomic(0.5f * acc, &g_accD);
}

// Kernel B: rigidity loss. E int32 [M,2], loaded 2 edges/LDG (int4), 4-edge
// unroll -> 8 outstanding one-sector float4 gathers per thread. Last block
// finalizes the loss and resets accumulators (replaces k_init/k_final).
__global__ void k_edge(const int* __restrict__ E, long long M,
                       const float* __restrict__ rig2,
                       float* __restrict__ out) {
    float acc = 0.0f;
    const int4* __restrict__ E4 = (const int4*)E;   // one int4 = 2 edges
    long long P = M >> 1;                            // edge-pairs
    long long stride = (long long)gridDim.x * blockDim.x;
    long long p = (long long)blockIdx.x * blockDim.x + threadIdx.x;

    for (; p + stride < P; p += 2 * stride) {
        int4 e0 = __ldg(E4 + p);
        int4 e1 = __ldg(E4 + p + stride);
        float4 a0 = __ldg(&g_W[e0.x]);
        float4 b0 = __ldg(&g_W[e0.y]);
        float4 a1 = __ldg(&g_W[e0.z]);
        float4 b1 = __ldg(&g_W[e0.w]);
        float4 a2 = __ldg(&g_W[e1.x]);
        float4 b2 = __ldg(&g_W[e1.y]);
        float4 a3 = __ldg(&g_W[e1.z]);
        float4 b3 = __ldg(&g_W[e1.w]);
        float dx0 = a0.x - b0.x, dy0 = a0.y - b0.y, dz0 = a0.z - b0.z;
        float dx1 = a1.x - b1.x, dy1 = a1.y - b1.y, dz1 = a1.z - b1.z;
        float dx2 = a2.x - b2.x, dy2 = a2.y - b2.y, dz2 = a2.z - b2.z;
        float dx3 = a3.x - b3.x, dy3 = a3.y - b3.y, dz3 = a3.z - b3.z;
        acc += fmaf(dx0, dx0, fmaf(dy0, dy0, dz0 * dz0));
        acc += fmaf(dx1, dx1, fmaf(dy1, dy1, dz1 * dz1));
        acc += fmaf(dx2, dx2, fmaf(dy2, dy2, dz2 * dz2));
        acc += fmaf(dx3, dx3, fmaf(dy3, dy3, dz3 * dz3));
    }
    if (p < P) {
        int4 e0 = __ldg(E4 + p);
        float4 a0 = __ldg(&g_W[e0.x]);
        float4 b0 = __ldg(&g_W[e0.y]);
        float4 a1 = __ldg(&g_W[e0.z]);
        float4 b1 = __ldg(&g_W[e0.w]);
        float dx0 = a0.x - b0.x, dy0 = a0.y - b0.y, dz0 = a0.z - b0.z;
        float dx1 = a1.x - b1.x, dy1 = a1.y - b1.y, dz1 = a1.z - b1.z;
        acc += fmaf(dx0, dx0, fmaf(dy0, dy0, dz0 * dz0));
        acc += fmaf(dx1, dx1, fmaf(dy1, dy1, dz1 * dz1));
    }
    // odd trailing edge (M odd), handled by thread 0 of block 0
    if ((M & 1LL) && blockIdx.x == 0 && threadIdx.x == 0) {
        int sidx = (int)__ldg(E + 2 * (M - 1));
        int didx = (int)__ldg(E + 2 * (M - 1) + 1);
        float4 a = __ldg(&g_W[sidx]);
        float4 b = __ldg(&g_W[didx]);
        float dx = a.x - b.x, dy = a.y - b.y, dz = a.z - b.z;
        acc += fmaf(dx, dx, fmaf(dy, dy, dz * dz));
    }

    block_reduce_atomic(0.5f * acc, &g_accR);

    // Last-block finalization (k_vertex completed before this launch started,
    // so g_accD is final; this block's accR atomic precedes the fence).
    if (threadIdx.x == 0) {
        __threadfence();
        unsigned t = atomicAdd(&g_ticket, 1u);
        if (t == gridDim.x - 1) {
            double aD = *(volatile double*)&g_accD;
            double aR = *(volatile double*)&g_accR;
            out[0] = (float)(aD + (double)__ldg(rig2) * aR);
            *(volatile double*)&g_accD = 0.0;
            *(volatile double*)&g_accR = 0.0;
            g_ticket = 0;
        }
    }
}

extern "C" void kernel_launch(void* const* d_in, const int* in_sizes, int n_in,
                              void* d_out, int out_size) {
    // Resolve inputs by element count:
    //   E: 2*M (largest, int32) | V, V_ref: 3*N each (V first)
    //   dist_field: 64^3        | rigidity2: 1
    const float* V     = nullptr;
    const float* Vref  = nullptr;
    const int*   E     = nullptr;
    const float* field = nullptr;
    const float* rig2  = nullptr;
    long long E_elems = 0;
    int       V_elems = 0;

    int big = 0;
    for (int k = 1; k < n_in; k++)
        if (in_sizes[k] > in_sizes[big]) big = k;
    E = (const int*)d_in[big];
    E_elems = in_sizes[big];

    for (int k = 0; k < n_in; k++) {
        if (k == big) continue;
        if (in_sizes[k] == 1) {
            rig2 = (const float*)d_in[k];
        } else if (in_sizes[k] == FGRID * FGRID * FGRID) {
            field = (const float*)d_in[k];
        } else if (!V) {
            V = (const float*)d_in[k];
            V_elems = in_sizes[k];
        } else {
            Vref = (const float*)d_in[k];
        }
    }

    float* out = (float*)d_out;
    int       N = V_elems / 3;
    long long M = E_elems / 2;

    // Persistent grids: ~8 blocks/SM on 148 SMs
    k_vertex<<<1184, 256>>>(V, Vref, field, N);
    k_edge<<<1184, 256>>>(E, M, rig2, out);
}

// round 8
// speedup vs baseline: 1.2042x; 1.2042x over previous
#include <cuda_runtime.h>
#include <cuda_bf16.h>

#define FGRID 64
#define TDIM  63          // tab y/z extent (x0,y0,z0 <= 62)
#define MAX_N 2000000
#define NCELLS (FGRID * TDIM * TDIM)   // 64*63*63 = 254016

// Device globals (allocation-free scratch). Zero at module load; k_main's
// last block resets accumulators after use so graph replays start clean.
__device__ double g_accD;
__device__ double g_accR;
__device__ unsigned g_ticket;
__device__ float4 g_W[MAX_N];     // W[i] = V[i]-V_ref[i], 16B padded: 1-sector gathers
__device__ float4 g_tab[NCELLS];  // corner table: (F(x,y,z),F(x,y,z+1),F(x,y+1,z),F(x,y+1,z+1))

__device__ __forceinline__ void block_reduce_atomic(float v, double* acc) {
    #pragma unroll
    for (int o = 16; o; o >>= 1)
        v += __shfl_xor_sync(0xffffffffu, v, o);
    __shared__ float warp_sums[32];
    int lane = threadIdx.x & 31;
    int wid  = threadIdx.x >> 5;
    if (lane == 0) warp_sums[wid] = v;
    __syncthreads();
    if (wid == 0) {
        int nw = (blockDim.x + 31) >> 5;
        float s = (lane < nw) ? warp_sums[lane] : 0.0f;
        #pragma unroll
        for (int o = 16; o; o >>= 1)
            s += __shfl_xor_sync(0xffffffffu, s, o);
        if (lane == 0) atomicAdd(acc, (double)s);
    }
    __syncthreads();   // warp_sums reused by second call
}

// Prep: phase 1 streams W = V - V_ref; phase 2 builds the corner table.
__global__ void k_prep(const float* __restrict__ V,
                       const float* __restrict__ Vref,
                       const float* __restrict__ field,
                       int N) {
    int stride = gridDim.x * blockDim.x;
    for (int i = blockIdx.x * blockDim.x + threadIdx.x; i < N; i += stride) {
        float wx = V[3 * i + 0] - Vref[3 * i + 0];
        float wy = V[3 * i + 1] - Vref[3 * i + 1];
        float wz = V[3 * i + 2] - Vref[3 * i + 2];
        g_W[i] = make_float4(wx, wy, wz, 0.0f);
    }
    for (int c = blockIdx.x * blockDim.x + threadIdx.x; c < NCELLS; c += stride) {
        int x = c / (TDIM * TDIM);
        int r = c % (TDIM * TDIM);
        int y = r / TDIM;
        int z = r % TDIM;
        int b = x * (FGRID * FGRID) + y * FGRID + z;
        g_tab[c] = make_float4(__ldg(field + b),
                               __ldg(field + b + 1),
                               __ldg(field + b + FGRID),
                               __ldg(field + b + FGRID + 1));
    }
}

// Main: every block runs the edge phase (rigidity) then the vertex phase
// (distance-field loss via 2 float4 corner-table loads). Last block finalizes.
__global__ void k_main(const int* __restrict__ E, long long M,
                       const float* __restrict__ V, int N,
                       const float* __restrict__ rig2,
                       float* __restrict__ out) {
    // ---- edge phase: 2 edges per int4 load, 4 edges (8 gathers) in flight ----
    float accR = 0.0f;
    {
        const int4* __restrict__ E4 = (const int4*)E;
        long long P = M >> 1;
        long long stride = (long long)gridDim.x * blockDim.x;
        long long p = (long long)blockIdx.x * blockDim.x + threadIdx.x;
        for (; p + stride < P; p += 2 * stride) {
            int4 e0 = __ldg(E4 + p);
            int4 e1 = __ldg(E4 + p + stride);
            float4 a0 = __ldg(&g_W[e0.x]);
            float4 b0 = __ldg(&g_W[e0.y]);
            float4 a1 = __ldg(&g_W[e0.z]);
            float4 b1 = __ldg(&g_W[e0.w]);
            float4 a2 = __ldg(&g_W[e1.x]);
            float4 b2 = __ldg(&g_W[e1.y]);
            float4 a3 = __ldg(&g_W[e1.z]);
            float4 b3 = __ldg(&g_W[e1.w]);
            float dx0 = a0.x - b0.x, dy0 = a0.y - b0.y, dz0 = a0.z - b0.z;
            float dx1 = a1.x - b1.x, dy1 = a1.y - b1.y, dz1 = a1.z - b1.z;
            float dx2 = a2.x - b2.x, dy2 = a2.y - b2.y, dz2 = a2.z - b2.z;
            float dx3 = a3.x - b3.x, dy3 = a3.y - b3.y, dz3 = a3.z - b3.z;
            accR += fmaf(dx0, dx0, fmaf(dy0, dy0, dz0 * dz0));
            accR += fmaf(dx1, dx1, fmaf(dy1, dy1, dz1 * dz1));
            accR += fmaf(dx2, dx2, fmaf(dy2, dy2, dz2 * dz2));
            accR += fmaf(dx3, dx3, fmaf(dy3, dy3, dz3 * dz3));
        }
        if (p < P) {
            int4 e0 = __ldg(E4 + p);
            float4 a0 = __ldg(&g_W[e0.x]);
            float4 b0 = __ldg(&g_W[e0.y]);
            float4 a1 = __ldg(&g_W[e0.z]);
            float4 b1 = __ldg(&g_W[e0.w]);
            float dx0 = a0.x - b0.x, dy0 = a0.y - b0.y, dz0 = a0.z - b0.z;
            float dx1 = a1.x - b1.x, dy1 = a1.y - b1.y, dz1 = a1.z - b1.z;
            accR += fmaf(dx0, dx0, fmaf(dy0, dy0, dz0 * dz0));
            accR += fmaf(dx1, dx1, fmaf(dy1, dy1, dz1 * dz1));
        }
        if ((M & 1LL) && blockIdx.x == 0 && threadIdx.x == 0) {
            int s = __ldg(E + 2 * (M - 1));
            int d = __ldg(E + 2 * (M - 1) + 1);
            float4 a = __ldg(&g_W[s]);
            float4 b = __ldg(&g_W[d]);
            float dx = a.x - b.x, dy = a.y - b.y, dz = a.z - b.z;
            accR += fmaf(dx, dx, fmaf(dy, dy, dz * dz));
        }
    }

    // ---- vertex phase: trilinear field loss, 2 corner-table loads/vertex ----
    float accD = 0.0f;
    {
        int stride = gridDim.x * blockDim.x;
        for (int i = blockIdx.x * blockDim.x + threadIdx.x; i < N; i += stride) {
            float vx = __ldg(V + 3 * i + 0);
            float vy = __ldg(V + 3 * i + 1);
            float vz = __ldg(V + 3 * i + 2);
            float cx = fmaxf(fminf(vx * 63.0f, 62.9999f), 0.0f);
            float cy = fmaxf(fminf(vy * 63.0f, 62.9999f), 0.0f);
            float cz = fmaxf(fminf(vz * 63.0f, 62.9999f), 0.0f);
            int x0 = (int)cx;  float fx = cx - (float)x0;
            int y0 = (int)cy;  float fy = cy - (float)y0;
            int z0 = (int)cz;  float fz = cz - (float)z0;
            int c = (x0 * TDIM + y0) * TDIM + z0;
            float4 t0 = __ldg(&g_tab[c]);                  // x0 plane
            float4 t1 = __ldg(&g_tab[c + TDIM * TDIM]);    // x0+1 plane
            float c00 = fmaf(fz, t0.y - t0.x, t0.x);
            float c01 = fmaf(fz, t0.w - t0.z, t0.z);
            float c10 = fmaf(fz, t1.y - t1.x, t1.x);
            float c11 = fmaf(fz, t1.w - t1.z, t1.z);
            float c0  = fmaf(fy, c01 - c00, c00);
            float c1  = fmaf(fy, c11 - c10, c10);
            float d   = fmaf(fx, c1 - c0, c0);
            accD = fmaf(d, d, accD);
        }
    }

    block_reduce_atomic(0.5f * accR, &g_accR);
    block_reduce_atomic(0.5f * accD, &g_accD);

    if (threadIdx.x == 0) {
        __threadfence();
        unsigned t = atomicAdd(&g_ticket, 1u);
        if (t == gridDim.x - 1) {
            double aD = *(volatile double*)&g_accD;
            double aR = *(volatile double*)&g_accR;
            out[0] = (float)(aD + (double)__ldg(rig2) * aR);
            *(volatile double*)&g_accD = 0.0;
            *(volatile double*)&g_accR = 0.0;
            g_ticket = 0;
        }
    }
}

extern "C" void kernel_launch(void* const* d_in, const int* in_sizes, int n_in,
                              void* d_out, int out_size) {
    // Resolve inputs by element count:
    //   E: 2*M (largest, int32) | V, V_ref: 3*N each (V first)
    //   dist_field: 64^3        | rigidity2: 1
    const float* V     = nullptr;
    const float* Vref  = nullptr;
    const int*   E     = nullptr;
    const float* field = nullptr;
    const float* rig2  = nullptr;
    long long E_elems = 0;
    int       V_elems = 0;

    int big = 0;
    for (int k = 1; k < n_in; k++)
        if (in_sizes[k] > in_sizes[big]) big = k;
    E = (const int*)d_in[big];
    E_elems = in_sizes[big];

    for (int k = 0; k < n_in; k++) {
        if (k == big) continue;
        if (in_sizes[k] == 1) {
            rig2 = (const float*)d_in[k];
        } else if (in_sizes[k] == FGRID * FGRID * FGRID) {
            field = (const float*)d_in[k];
        } else if (!V) {
            V = (const float*)d_in[k];
            V_elems = in_sizes[k];
        } else {
            Vref = (const float*)d_in[k];
        }
    }

    float* out = (float*)d_out;
    int       N = V_elems / 3;
    long long M = E_elems / 2;

    k_prep<<<1184, 256>>>(V, Vref, field, N);
    k_main<<<1480, 256>>>(E, M, V, N, rig2, out);
}